// round 1
// baseline (speedup 1.0000x reference)
#include <cuda_runtime.h>
#include <cstdint>

// ---------------------------------------------------------------------------
// Kagome 3x3 conv: pad 16x16 -> 18x18, 37 boundary copies, VALID 3x3 conv,
// +bias, *mask.  B=2048, Cin=Cout=128, fp32.
//
// CTA: one image (blockIdx.y) x 64 output channels (blockIdx.x in {0,1}).
// 256 threads: coT = tid&7 (8 co-groups of 8), pxT = tid>>3 (32 half-rows of
// 8 pixels).  Per-thread tile: 8 px x 8 co, accumulated as f32x2 pairs via
// packed fma.rn.f32x2 (2x FFMA-pipe throughput on sm_103a).
// Cin processed in chunks of 8: padded x tile + W[ci][k][co] staged in SMEM.
// ---------------------------------------------------------------------------

#define CK 8          // Cin channels per chunk
#define NCHUNK 16     // 128 / CK

// 37 boundary-condition copies: padded[FDR,FDC] = x[FSR-1, FSC-1]
// (all sources are interior => read directly from original x; gather semantics)
__constant__ int FDR[37] = {1,1,2,3,4,4,6,7,8,10,11,12,14,14,15,16,17,17,16,15,14,14,12,10,8,6,4,4,3,2,5,9,13,15,17,15,13};
__constant__ int FDC[37] = {3,5,7,9,10,11,13,13,14,15,15,16,15,16,15,14,13,11,9,7,6,5,3,2,1,0,0,1,1,2,0,2,4,8,12,14,16};
__constant__ int FSR[37] = {13,13,14,15,16,16,6,7,8,10,11,12,2,2,3,4,5,5,4,3,2,2,12,10,8,6,16,16,15,14,5,9,1,3,5,3,1};
__constant__ int FSC[37] = {15,5,7,9,10,11,1,1,2,3,3,4,3,4,3,2,1,11,9,7,6,5,15,14,13,12,12,13,13,14,12,14,4,8,12,2,4};

// keep-mask per output row: bit c set => keep (derived from _make_mask rules)
__constant__ unsigned MASKROW[16] = {
    0x0008u, 0x003Cu, 0x00FEu, 0x01FEu,
    0x0FFFu, 0x0FFFu, 0x0FFFu, 0x1FFEu,
    0x3FFCu, 0x3FFCu, 0x3FFCu, 0x7FF8u,
    0x7FF0u, 0x3FC0u, 0x1F00u, 0x1E00u
};

__device__ __forceinline__ unsigned long long pack2(float a, float b) {
    unsigned long long r;
    asm("mov.b64 %0, {%1, %2};" : "=l"(r) : "f"(a), "f"(b));
    return r;
}
__device__ __forceinline__ void unpack2(unsigned long long v, float& a, float& b) {
    asm("mov.b64 {%0, %1}, %2;" : "=f"(a), "=f"(b) : "l"(v));
}
__device__ __forceinline__ unsigned long long fma2(unsigned long long a,
                                                   unsigned long long b,
                                                   unsigned long long c) {
    unsigned long long d;
    asm("fma.rn.f32x2 %0, %1, %2, %3;" : "=l"(d) : "l"(a), "l"(b), "l"(c));
    return d;
}

__global__ void __launch_bounds__(256)
kagome_conv_kernel(const float* __restrict__ x,
                   const float* __restrict__ W,
                   const float* __restrict__ b,
                   float* __restrict__ out) {
    __shared__ float xs[CK][18 * 18];      // padded input tile per ci-chunk
    __shared__ float ws[CK][9][64];        // W[ci][k][co] for this CTA's 64 co

    const int n      = blockIdx.y;
    const int coBase = blockIdx.x * 64;
    const int tid    = threadIdx.x;
    const int coT    = tid & 7;            // 0..7  -> co = coBase + coT*8 .. +7
    const int pxT    = tid >> 3;           // 0..31 -> half-row of 8 pixels
    const int r      = pxT >> 1;           // output row 0..15
    const int c0     = (pxT & 1) * 8;      // output col base 0 or 8

    // zero whole padded tile once; non-fixup border cells stay 0 forever
    for (int i = tid; i < CK * 324; i += 256) (&xs[0][0])[i] = 0.f;

    unsigned long long acc[8][4];
    #pragma unroll
    for (int p = 0; p < 8; p++)
        #pragma unroll
        for (int q = 0; q < 4; q++) acc[p][q] = 0ull;

    const float* xg = x + (size_t)n * 128 * 256;
    const float* Wg = W + (size_t)coBase * 128 * 9;

    for (int cb = 0; cb < 128; cb += CK) {
        __syncthreads();   // zero / previous compute done

        // phase 1: interior fill (coalesced): 8 floats per thread
        #pragma unroll
        for (int i = 0; i < CK; i++) {
            int idx = tid + i * 256;
            int ci = idx >> 8, px = idx & 255;
            xs[ci][(px >> 4) * 18 + (px & 15) + 19] = xg[(cb + ci) * 256 + px];
        }
        __syncthreads();   // interior visible before fixups overwrite

        // phase 2a: 37 boundary fixups per channel (reads original x from gmem)
        for (int j = tid; j < CK * 37; j += 256) {
            int ci = j / 37, f = j - ci * 37;
            xs[ci][FDR[f] * 18 + FDC[f]] =
                xg[(cb + ci) * 256 + (FSR[f] - 1) * 16 + (FSC[f] - 1)];
        }
        // phase 2b: stage W chunk as [ci][k][co]
        #pragma unroll
        for (int i = 0; i < CK * 9 * 64 / 256; i++) {   // 18 iters
            int idx = tid + i * 256;
            int ci = idx / 576, rem = idx - ci * 576;
            int k = rem >> 6, co = rem & 63;
            ws[ci][k][co] = Wg[co * 1152 + (cb + ci) * 9 + k];
        }
        __syncthreads();

        // compute: 8 ci x 9 taps x (8 px x 8 co) per thread
        #pragma unroll 1
        for (int ci = 0; ci < CK; ci++) {
            const float* xb = &xs[ci][r * 18 + c0];
            float x0[10], x1[10], x2[10];
            #pragma unroll
            for (int j = 0; j < 10; j++) {
                x0[j] = xb[j];
                x1[j] = xb[18 + j];
                x2[j] = xb[36 + j];
            }
            #pragma unroll
            for (int k = 0; k < 9; k++) {
                const int kr = k / 3, kc = k - kr * 3;
                const float4* wp =
                    reinterpret_cast<const float4*>(&ws[ci][k][coT * 8]);
                float4 wa = wp[0], wb4 = wp[1];
                unsigned long long w0 = pack2(wa.x, wa.y);
                unsigned long long w1 = pack2(wa.z, wa.w);
                unsigned long long w2 = pack2(wb4.x, wb4.y);
                unsigned long long w3 = pack2(wb4.z, wb4.w);
                const float* xr = (kr == 0) ? x0 : (kr == 1) ? x1 : x2;
                #pragma unroll
                for (int p = 0; p < 8; p++) {
                    float xv = xr[p + kc];
                    unsigned long long xd = pack2(xv, xv);
                    acc[p][0] = fma2(xd, w0, acc[p][0]);
                    acc[p][1] = fma2(xd, w1, acc[p][1]);
                    acc[p][2] = fma2(xd, w2, acc[p][2]);
                    acc[p][3] = fma2(xd, w3, acc[p][3]);
                }
            }
        }
    }

    // epilogue: +bias, *mask, store
    const unsigned mrow = MASKROW[r];
    const int coLoc = coBase + coT * 8;
    float bias[8];
    #pragma unroll
    for (int j = 0; j < 8; j++) bias[j] = b[coLoc + j];

    const size_t outBase = ((size_t)n * 128 + coLoc) * 256 + r * 16 + c0;
    #pragma unroll
    for (int q = 0; q < 4; q++) {
        float o0[8], o1[8];
        #pragma unroll
        for (int p = 0; p < 8; p++) {
            float v0, v1;
            unpack2(acc[p][q], v0, v1);
            float m = ((mrow >> (c0 + p)) & 1u) ? 1.f : 0.f;
            o0[p] = (v0 + bias[2 * q]) * m;
            o1[p] = (v1 + bias[2 * q + 1]) * m;
        }
        float4* d0 = reinterpret_cast<float4*>(out + outBase + (size_t)(2 * q) * 256);
        float4* d1 = reinterpret_cast<float4*>(out + outBase + (size_t)(2 * q + 1) * 256);
        d0[0] = make_float4(o0[0], o0[1], o0[2], o0[3]);
        d0[1] = make_float4(o0[4], o0[5], o0[6], o0[7]);
        d1[0] = make_float4(o1[0], o1[1], o1[2], o1[3]);
        d1[1] = make_float4(o1[4], o1[5], o1[6], o1[7]);
    }
}

extern "C" void kernel_launch(void* const* d_in, const int* in_sizes, int n_in,
                              void* d_out, int out_size) {
    (void)in_sizes; (void)n_in; (void)out_size;
    const float* x = (const float*)d_in[0];
    const float* W = (const float*)d_in[1];
    const float* b = (const float*)d_in[2];
    float* out = (float*)d_out;

    dim3 grid(2, 2048);
    kagome_conv_kernel<<<grid, 256>>>(x, W, b, out);
}